// round 10
// baseline (speedup 1.0000x reference)
#include <cuda_runtime.h>
#include <math.h>

#define BB 2
#define SS 2048
#define DD 1024
#define HH 16
#define DH 64
#define MM (BB * SS)   // 4096

// Scratch. g_q/g_k/g_v hold TF32 BIT PATTERNS (written by the QKV epilogue);
// g_q additionally pre-scaled by 1/8. g_att is fp32.
__device__ float g_q[BB * HH * SS * DH];
__device__ float g_k[BB * HH * SS * DH];
__device__ float g_v[BB * HH * SS * DH];
__device__ float g_att[BB * SS * DD];

// ---------------------------------------------------------------------------
// tf32 helpers. 2-term split: hi = RN_tf32(x), lo = x - hi (exact).
// ---------------------------------------------------------------------------
__device__ __forceinline__ void split_tf32(float x, unsigned& hi, unsigned& lo) {
    unsigned h;
    asm("cvt.rna.tf32.f32 %0, %1;\n" : "=r"(h) : "f"(x));
    hi = h;
    lo = __float_as_uint(x - __uint_as_float(h));
}
__device__ __forceinline__ unsigned f2tf32(float x) {
    unsigned r;
    asm("cvt.rna.tf32.f32 %0, %1;\n" : "=r"(r) : "f"(x));
    return r;
}
__device__ __forceinline__ void mma_tf32(float& c0, float& c1, float& c2, float& c3,
                                         unsigned a0, unsigned a1, unsigned a2, unsigned a3,
                                         unsigned b0, unsigned b1) {
    asm volatile(
        "mma.sync.aligned.m16n8k8.row.col.f32.tf32.tf32.f32 "
        "{%0,%1,%2,%3}, {%4,%5,%6,%7}, {%8,%9}, {%0,%1,%2,%3};\n"
        : "+f"(c0), "+f"(c1), "+f"(c2), "+f"(c3)
        : "r"(a0), "r"(a1), "r"(a2), "r"(a3), "r"(b0), "r"(b1));
}

// cp.async helpers
__device__ __forceinline__ unsigned smem_u32(const void* p) {
    return (unsigned)__cvta_generic_to_shared(p);
}
__device__ __forceinline__ void cp16(unsigned s, const void* g) {
    asm volatile("cp.async.cg.shared.global [%0], [%1], 16;\n" :: "r"(s), "l"(g));
}
#define CP_COMMIT() asm volatile("cp.async.commit_group;\n" ::: "memory")
#define CP_WAIT1()  asm volatile("cp.async.wait_group 1;\n" ::: "memory")

// ---------------------------------------------------------------------------
// NT GEMM via 2-term tf32 tensor cores, cp.async double-buffered tiles.
// C[m,n] = sum_k A[m,k] * W[n,k] (+bias).
// Block tile 128x128, 8 warps, warp tile 32(m)x64(n), k-chunk 32.
// mode 0: fused QKV. A = x, blockIdx.z picks Wq/Wk/Wv; outputs written as
//         TF32 BITS into g_q (scaled 1/8) / g_k / g_v, [B,H,S,Dh] layout.
// mode 3: A = g_att, W = W0 (= wo), out -> Cext ([B,S,D]) fp32 with bias.
// ---------------------------------------------------------------------------
__global__ void __launch_bounds__(256, 2) gemm_tf32(const float* __restrict__ A,
                                                    const float* __restrict__ W0,
                                                    const float* __restrict__ W1,
                                                    const float* __restrict__ W2,
                                                    const float* __restrict__ bias,
                                                    float* __restrict__ Cext,
                                                    int mode) {
    __shared__ float As[2][128][36];
    __shared__ float Ws[2][128][36];

    const int t    = threadIdx.x;
    const int lane = t & 31;
    const int warp = t >> 5;
    const int wm   = warp >> 1;      // 0..3  (m position)
    const int wn   = warp & 1;       // 0..1  (n position)
    const int g    = lane >> 2;      // groupID 0..7
    const int tg   = lane & 3;       // thread in group 0..3

    const int m0 = blockIdx.y * 128;
    const int n0 = blockIdx.x * 128;
    const int z  = blockIdx.z;

    const float* Asrc = (mode == 3) ? g_att : A;
    const float* W = (mode == 3) ? W0 : (z == 0) ? W0 : (z == 1) ? W1 : W2;
    float* C = (mode == 3) ? Cext : (z == 0) ? g_q : (z == 1) ? g_k : g_v;

    auto load_chunk = [&](int k0, int bufi) {
#pragma unroll
        for (int i = 0; i < 4; i++) {
            int idx = t + i * 256;
            int row = idx >> 3;
            int fc  = (idx & 7) * 4;
            cp16(smem_u32(&As[bufi][row][fc]), Asrc + (size_t)(m0 + row) * 1024 + k0 + fc);
            cp16(smem_u32(&Ws[bufi][row][fc]), W + (size_t)(n0 + row) * 1024 + k0 + fc);
        }
    };

    float c[2][8][4];
#pragma unroll
    for (int mi = 0; mi < 2; mi++)
#pragma unroll
        for (int ni = 0; ni < 8; ni++)
#pragma unroll
            for (int e = 0; e < 4; e++) c[mi][ni][e] = 0.f;

    load_chunk(0, 0);  CP_COMMIT();
    load_chunk(32, 1); CP_COMMIT();

    for (int kc = 0; kc < 32; kc++) {
        CP_WAIT1();
        __syncthreads();
        const int bi = kc & 1;

#pragma unroll
        for (int kk = 0; kk < 4; kk++) {
            const int kb = kk * 8;
            unsigned ah[2][4], al[2][4], bh[8][2];
#pragma unroll
            for (int mi = 0; mi < 2; mi++) {
                const int rb = wm * 32 + mi * 16;
                split_tf32(As[bi][rb + g][kb + tg],          ah[mi][0], al[mi][0]);
                split_tf32(As[bi][rb + g + 8][kb + tg],      ah[mi][1], al[mi][1]);
                split_tf32(As[bi][rb + g][kb + tg + 4],      ah[mi][2], al[mi][2]);
                split_tf32(As[bi][rb + g + 8][kb + tg + 4],  ah[mi][3], al[mi][3]);
            }
#pragma unroll
            for (int ni = 0; ni < 8; ni++) {
                const int nb = wn * 64 + ni * 8;
                bh[ni][0] = f2tf32(Ws[bi][nb + g][kb + tg]);
                bh[ni][1] = f2tf32(Ws[bi][nb + g][kb + tg + 4]);
            }
#pragma unroll
            for (int mi = 0; mi < 2; mi++)
#pragma unroll
                for (int ni = 0; ni < 8; ni++) {
                    mma_tf32(c[mi][ni][0], c[mi][ni][1], c[mi][ni][2], c[mi][ni][3],
                             ah[mi][0], ah[mi][1], ah[mi][2], ah[mi][3],
                             bh[ni][0], bh[ni][1]);
                    mma_tf32(c[mi][ni][0], c[mi][ni][1], c[mi][ni][2], c[mi][ni][3],
                             al[mi][0], al[mi][1], al[mi][2], al[mi][3],
                             bh[ni][0], bh[ni][1]);
                }
        }

        __syncthreads();
        if (kc < 30) load_chunk((kc + 2) * 32, bi);
        CP_COMMIT();
    }

    // Epilogue. mode 0: convert to tf32 bits here (free), so the attention
    // hot loop never converts. Q additionally pre-scaled by 1/8 (exact).
#pragma unroll
    for (int mi = 0; mi < 2; mi++) {
#pragma unroll
        for (int ni = 0; ni < 8; ni++) {
            int mA = m0 + wm * 32 + mi * 16 + g;
            int mB = mA + 8;
            int n  = n0 + wn * 64 + ni * 8 + 2 * tg;
            if (mode == 3) {
                float bx = bias[n], by = bias[n + 1];
                *(float2*)(C + (size_t)mA * 1024 + n) =
                    make_float2(c[mi][ni][0] + bx, c[mi][ni][1] + by);
                *(float2*)(C + (size_t)mB * 1024 + n) =
                    make_float2(c[mi][ni][2] + bx, c[mi][ni][3] + by);
            } else {
                int h  = n >> 6;
                int dh = n & 63;
                float sc = (z == 0) ? 0.125f : 1.0f;
                {
                    int b = mA >> 11, s = mA & 2047;
                    *(float2*)(C + (size_t)((b * HH + h) * SS + s) * DH + dh) =
                        make_float2(__uint_as_float(f2tf32(c[mi][ni][0] * sc)),
                                    __uint_as_float(f2tf32(c[mi][ni][1] * sc)));
                }
                {
                    int b = mB >> 11, s = mB & 2047;
                    *(float2*)(C + (size_t)((b * HH + h) * SS + s) * DH + dh) =
                        make_float2(__uint_as_float(f2tf32(c[mi][ni][2] * sc)),
                                    __uint_as_float(f2tf32(c[mi][ni][3] * sc)));
                }
            }
        }
    }
}

// ---------------------------------------------------------------------------
// Flash attention via tensor cores, cp.async double-buffered K/V tiles.
// Block = 64 query rows, 4 warps (16 rows each), 64-key tiles through SMEM.
// Q/K/V arrive as tf32 bits (converted in the QKV epilogue) -> the hot loop
// is pure LDS + HMMA. QK^T: single tf32. P*V: tf32 via SMEM Ps round-trip
// (tf32 quantization of P and V: 4x finer than bf16 -> rel_err ~3e-4 stack).
// Writes g_att [B,S,D] fp32.
// ---------------------------------------------------------------------------
__global__ void __launch_bounds__(128, 2) attn_mma() {
    const int b = blockIdx.z;
    const int h = blockIdx.y;
    const int t = threadIdx.x;
    const int warp = t >> 5;
    const int lane = t & 31;
    const int g  = lane >> 2;   // 0..7
    const int tg = lane & 3;    // 0..3
    const int qrow0 = blockIdx.x * 64 + warp * 16;
    const size_t bh = (size_t)(b * HH + h) * SS;

    __shared__ unsigned Ks[2][64][68];   // tf32 K bits (4g+tg conflict-free)
    __shared__ unsigned Vs[2][64][72];   // tf32 V bits (8tg+g conflict-free)
    __shared__ unsigned Ps[64][68];      // tf32 P (per-warp 16-row slabs)

    auto load_kv = [&](int kt, int bufi) {
#pragma unroll
        for (int i = 0; i < 8; i++) {
            int idx = t + i * 128;
            int r = idx >> 4;
            int c = (idx & 15) * 4;
            cp16(smem_u32(&Ks[bufi][r][c]), g_k + (bh + kt + r) * DH + c);
            cp16(smem_u32(&Vs[bufi][r][c]), g_v + (bh + kt + r) * DH + c);
        }
    };

    // Q fragments: tf32 bits straight from gmem (already scaled 1/8).
    unsigned qh[8][4];
    {
        const unsigned* Q = (const unsigned*)(g_q + (bh + qrow0) * DH);
#pragma unroll
        for (int kb = 0; kb < 8; kb++) {
            qh[kb][0] = Q[g * DH + kb * 8 + tg];
            qh[kb][1] = Q[(g + 8) * DH + kb * 8 + tg];
            qh[kb][2] = Q[g * DH + kb * 8 + tg + 4];
            qh[kb][3] = Q[(g + 8) * DH + kb * 8 + tg + 4];
        }
    }

    float o[8][4];
#pragma unroll
    for (int ni = 0; ni < 8; ni++)
#pragma unroll
        for (int e = 0; e < 4; e++) o[ni][e] = 0.f;
    float mi0 = -1e30f, mi8 = -1e30f, li0 = 0.f, li8 = 0.f;

    load_kv(0, 0);  CP_COMMIT();
    load_kv(64, 1); CP_COMMIT();

    for (int it = 0; it < 32; it++) {
        CP_WAIT1();
        __syncthreads();
        const int bi = it & 1;

        // S = Q * K^T (single tf32), warp computes 16x64 scores.
        float s[8][4];
#pragma unroll
        for (int ni = 0; ni < 8; ni++)
#pragma unroll
            for (int e = 0; e < 4; e++) s[ni][e] = 0.f;

#pragma unroll
        for (int kb = 0; kb < 8; kb++) {
#pragma unroll
            for (int ni = 0; ni < 8; ni++) {
                unsigned b0h = Ks[bi][ni * 8 + g][kb * 8 + tg];
                unsigned b1h = Ks[bi][ni * 8 + g][kb * 8 + tg + 4];
                mma_tf32(s[ni][0], s[ni][1], s[ni][2], s[ni][3],
                         qh[kb][0], qh[kb][1], qh[kb][2], qh[kb][3], b0h, b1h);
            }
        }

        // Online softmax. Rows: g (elements 0,1) and g+8 (elements 2,3).
        float t0 = mi0, t8 = mi8;
#pragma unroll
        for (int ni = 0; ni < 8; ni++) {
            t0 = fmaxf(t0, fmaxf(s[ni][0], s[ni][1]));
            t8 = fmaxf(t8, fmaxf(s[ni][2], s[ni][3]));
        }
        t0 = fmaxf(t0, __shfl_xor_sync(0xffffffffu, t0, 1));
        t0 = fmaxf(t0, __shfl_xor_sync(0xffffffffu, t0, 2));
        t8 = fmaxf(t8, __shfl_xor_sync(0xffffffffu, t8, 1));
        t8 = fmaxf(t8, __shfl_xor_sync(0xffffffffu, t8, 2));

        float c0 = __expf(mi0 - t0);
        float c8 = __expf(mi8 - t8);
        mi0 = t0; mi8 = t8;
        li0 *= c0; li8 *= c8;

        float rs0 = 0.f, rs8 = 0.f;
#pragma unroll
        for (int ni = 0; ni < 8; ni++) {
            o[ni][0] *= c0; o[ni][1] *= c0;
            o[ni][2] *= c8; o[ni][3] *= c8;
            float p0 = __expf(s[ni][0] - mi0);
            float p1 = __expf(s[ni][1] - mi0);
            float p2 = __expf(s[ni][2] - mi8);
            float p3 = __expf(s[ni][3] - mi8);
            rs0 += p0 + p1;
            rs8 += p2 + p3;
            Ps[warp * 16 + g][ni * 8 + 2 * tg]         = f2tf32(p0);
            Ps[warp * 16 + g][ni * 8 + 2 * tg + 1]     = f2tf32(p1);
            Ps[warp * 16 + 8 + g][ni * 8 + 2 * tg]     = f2tf32(p2);
            Ps[warp * 16 + 8 + g][ni * 8 + 2 * tg + 1] = f2tf32(p3);
        }
        li0 += rs0; li8 += rs8;
        __syncwarp();

        // O += P * V (tf32; P and V already tf32 bits, pure LDS + HMMA).
#pragma unroll
        for (int kb = 0; kb < 8; kb++) {
            unsigned a0 = Ps[warp * 16 + g][kb * 8 + tg];
            unsigned a1 = Ps[warp * 16 + 8 + g][kb * 8 + tg];
            unsigned a2 = Ps[warp * 16 + g][kb * 8 + tg + 4];
            unsigned a3 = Ps[warp * 16 + 8 + g][kb * 8 + tg + 4];
#pragma unroll
            for (int ni = 0; ni < 8; ni++) {
                mma_tf32(o[ni][0], o[ni][1], o[ni][2], o[ni][3],
                         a0, a1, a2, a3,
                         Vs[bi][kb * 8 + tg][ni * 8 + g],
                         Vs[bi][kb * 8 + tg + 4][ni * 8 + g]);
            }
        }

        __syncthreads();
        if (it < 30) load_kv((it + 2) * 64, bi);
        CP_COMMIT();
    }

    li0 += __shfl_xor_sync(0xffffffffu, li0, 1);
    li0 += __shfl_xor_sync(0xffffffffu, li0, 2);
    li8 += __shfl_xor_sync(0xffffffffu, li8, 1);
    li8 += __shfl_xor_sync(0xffffffffu, li8, 2);
    float inv0 = 1.f / li0;
    float inv8 = 1.f / li8;

    float* O0 = g_att + ((size_t)b * SS + qrow0 + g) * DD + h * DH;
    float* O8 = g_att + ((size_t)b * SS + qrow0 + 8 + g) * DD + h * DH;
#pragma unroll
    for (int ni = 0; ni < 8; ni++) {
        *(float2*)(O0 + ni * 8 + 2 * tg) = make_float2(o[ni][0] * inv0, o[ni][1] * inv0);
        *(float2*)(O8 + ni * 8 + 2 * tg) = make_float2(o[ni][2] * inv8, o[ni][3] * inv8);
    }
}

extern "C" void kernel_launch(void* const* d_in, const int* in_sizes, int n_in,
                              void* d_out, int out_size) {
    const float* x  = (const float*)d_in[0];
    const float* wq = (const float*)d_in[1];
    const float* wk = (const float*)d_in[2];
    const float* wv = (const float*)d_in[3];
    const float* wo = (const float*)d_in[4];
    const float* bo = (const float*)d_in[5];
    float* out = (float*)d_out;

    dim3 gqkv(DD / 128, MM / 128, 3);   // (8, 32, 3) fused Q/K/V projections
    gemm_tf32<<<gqkv, 256>>>(x, wq, wk, wv, nullptr, nullptr, 0);

    dim3 ga(SS / 64, HH, BB);           // (32, 16, 2)
    attn_mma<<<ga, 128>>>();

    dim3 go(DD / 128, MM / 128, 1);
    gemm_tf32<<<go, 256>>>(nullptr, wo, nullptr, nullptr, bo, out, 3);
}

// round 11
// speedup vs baseline: 1.2617x; 1.2617x over previous
#include <cuda_runtime.h>
#include <math.h>

#define BB 2
#define SS 2048
#define DD 1024
#define HH 16
#define DH 64
#define MM (BB * SS)   // 4096

// Scratch. g_q/g_k/g_v hold TF32 BIT PATTERNS (written by the QKV epilogue);
// g_q additionally pre-scaled by 1/8. g_att is fp32.
__device__ float g_q[BB * HH * SS * DH];
__device__ float g_k[BB * HH * SS * DH];
__device__ float g_v[BB * HH * SS * DH];
__device__ float g_att[BB * SS * DD];

// ---------------------------------------------------------------------------
// tf32 helpers
// ---------------------------------------------------------------------------
__device__ __forceinline__ unsigned f2tf32(float x) {
    unsigned r;
    asm("cvt.rna.tf32.f32 %0, %1;\n" : "=r"(r) : "f"(x));
    return r;
}
__device__ __forceinline__ void mma_tf32(float& c0, float& c1, float& c2, float& c3,
                                         unsigned a0, unsigned a1, unsigned a2, unsigned a3,
                                         unsigned b0, unsigned b1) {
    asm volatile(
        "mma.sync.aligned.m16n8k8.row.col.f32.tf32.tf32.f32 "
        "{%0,%1,%2,%3}, {%4,%5,%6,%7}, {%8,%9}, {%0,%1,%2,%3};\n"
        : "+f"(c0), "+f"(c1), "+f"(c2), "+f"(c3)
        : "r"(a0), "r"(a1), "r"(a2), "r"(a3), "r"(b0), "r"(b1));
}

// cp.async helpers
__device__ __forceinline__ unsigned smem_u32(const void* p) {
    return (unsigned)__cvta_generic_to_shared(p);
}
__device__ __forceinline__ void cp16(unsigned s, const void* g) {
    asm volatile("cp.async.cg.shared.global [%0], [%1], 16;\n" :: "r"(s), "l"(g));
}
#define CP_COMMIT() asm volatile("cp.async.commit_group;\n" ::: "memory")
#define CP_WAIT1()  asm volatile("cp.async.wait_group 1;\n" ::: "memory")

// ---------------------------------------------------------------------------
// NT GEMM, single-tf32 x single-tf32 (RNA both operands; zero-mean error
// ~2e-4 relative per output). cp.async double-buffered tiles.
// C[m,n] = sum_k A[m,k] * W[n,k] (+bias).
// Block tile 128x128, 8 warps, warp tile 32(m)x64(n), k-chunk 32.
// mode 0: fused QKV. A = x, blockIdx.z picks Wq/Wk/Wv; outputs written as
//         TF32 BITS into g_q (scaled 1/8) / g_k / g_v, [B,H,S,Dh] layout.
// mode 3: A = g_att, W = W0 (= wo), out -> Cext ([B,S,D]) fp32 with bias.
// ---------------------------------------------------------------------------
__global__ void __launch_bounds__(256, 2) gemm_tf32(const float* __restrict__ A,
                                                    const float* __restrict__ W0,
                                                    const float* __restrict__ W1,
                                                    const float* __restrict__ W2,
                                                    const float* __restrict__ bias,
                                                    float* __restrict__ Cext,
                                                    int mode) {
    __shared__ float As[2][128][36];
    __shared__ float Ws[2][128][36];

    const int t    = threadIdx.x;
    const int lane = t & 31;
    const int warp = t >> 5;
    const int wm   = warp >> 1;      // 0..3  (m position)
    const int wn   = warp & 1;       // 0..1  (n position)
    const int g    = lane >> 2;      // groupID 0..7
    const int tg   = lane & 3;       // thread in group 0..3

    const int m0 = blockIdx.y * 128;
    const int n0 = blockIdx.x * 128;
    const int z  = blockIdx.z;

    const float* Asrc = (mode == 3) ? g_att : A;
    const float* W = (mode == 3) ? W0 : (z == 0) ? W0 : (z == 1) ? W1 : W2;
    float* C = (mode == 3) ? Cext : (z == 0) ? g_q : (z == 1) ? g_k : g_v;

    auto load_chunk = [&](int k0, int bufi) {
#pragma unroll
        for (int i = 0; i < 4; i++) {
            int idx = t + i * 256;
            int row = idx >> 3;
            int fc  = (idx & 7) * 4;
            cp16(smem_u32(&As[bufi][row][fc]), Asrc + (size_t)(m0 + row) * 1024 + k0 + fc);
            cp16(smem_u32(&Ws[bufi][row][fc]), W + (size_t)(n0 + row) * 1024 + k0 + fc);
        }
    };

    float c[2][8][4];
#pragma unroll
    for (int mi = 0; mi < 2; mi++)
#pragma unroll
        for (int ni = 0; ni < 8; ni++)
#pragma unroll
            for (int e = 0; e < 4; e++) c[mi][ni][e] = 0.f;

    load_chunk(0, 0);  CP_COMMIT();
    load_chunk(32, 1); CP_COMMIT();

    for (int kc = 0; kc < 32; kc++) {
        CP_WAIT1();
        __syncthreads();
        const int bi = kc & 1;

#pragma unroll
        for (int kk = 0; kk < 4; kk++) {
            const int kb = kk * 8;
            unsigned ah[2][4], bh[8][2];
#pragma unroll
            for (int mi = 0; mi < 2; mi++) {
                const int rb = wm * 32 + mi * 16;
                ah[mi][0] = f2tf32(As[bi][rb + g][kb + tg]);
                ah[mi][1] = f2tf32(As[bi][rb + g + 8][kb + tg]);
                ah[mi][2] = f2tf32(As[bi][rb + g][kb + tg + 4]);
                ah[mi][3] = f2tf32(As[bi][rb + g + 8][kb + tg + 4]);
            }
#pragma unroll
            for (int ni = 0; ni < 8; ni++) {
                const int nb = wn * 64 + ni * 8;
                bh[ni][0] = f2tf32(Ws[bi][nb + g][kb + tg]);
                bh[ni][1] = f2tf32(Ws[bi][nb + g][kb + tg + 4]);
            }
#pragma unroll
            for (int mi = 0; mi < 2; mi++)
#pragma unroll
                for (int ni = 0; ni < 8; ni++) {
                    mma_tf32(c[mi][ni][0], c[mi][ni][1], c[mi][ni][2], c[mi][ni][3],
                             ah[mi][0], ah[mi][1], ah[mi][2], ah[mi][3],
                             bh[ni][0], bh[ni][1]);
                }
        }

        __syncthreads();
        if (kc < 30) load_chunk((kc + 2) * 32, bi);
        CP_COMMIT();
    }

    // Epilogue. mode 0: convert to tf32 bits here (free), so the attention
    // hot loop never converts. Q additionally pre-scaled by 1/8 (exact).
#pragma unroll
    for (int mi = 0; mi < 2; mi++) {
#pragma unroll
        for (int ni = 0; ni < 8; ni++) {
            int mA = m0 + wm * 32 + mi * 16 + g;
            int mB = mA + 8;
            int n  = n0 + wn * 64 + ni * 8 + 2 * tg;
            if (mode == 3) {
                float bx = bias[n], by = bias[n + 1];
                *(float2*)(C + (size_t)mA * 1024 + n) =
                    make_float2(c[mi][ni][0] + bx, c[mi][ni][1] + by);
                *(float2*)(C + (size_t)mB * 1024 + n) =
                    make_float2(c[mi][ni][2] + bx, c[mi][ni][3] + by);
            } else {
                int h  = n >> 6;
                int dh = n & 63;
                float sc = (z == 0) ? 0.125f : 1.0f;
                {
                    int b = mA >> 11, s = mA & 2047;
                    *(float2*)(C + (size_t)((b * HH + h) * SS + s) * DH + dh) =
                        make_float2(__uint_as_float(f2tf32(c[mi][ni][0] * sc)),
                                    __uint_as_float(f2tf32(c[mi][ni][1] * sc)));
                }
                {
                    int b = mB >> 11, s = mB & 2047;
                    *(float2*)(C + (size_t)((b * HH + h) * SS + s) * DH + dh) =
                        make_float2(__uint_as_float(f2tf32(c[mi][ni][2] * sc)),
                                    __uint_as_float(f2tf32(c[mi][ni][3] * sc)));
                }
            }
        }
    }
}

// ---------------------------------------------------------------------------
// Flash attention via tensor cores, cp.async double-buffered K/V tiles.
// Block = 64 query rows, 4 warps (16 rows each), 64-key tiles through SMEM.
// Q/K/V arrive as tf32 bits (converted in the QKV epilogue) -> the hot loop
// is pure LDS + HMMA. QK^T: single tf32. P*V: tf32 via SMEM Ps round-trip.
// Writes g_att [B,S,D] fp32.  (R10-proven: stack rel_err ~1.7e-4.)
// ---------------------------------------------------------------------------
__global__ void __launch_bounds__(128, 2) attn_mma() {
    const int b = blockIdx.z;
    const int h = blockIdx.y;
    const int t = threadIdx.x;
    const int warp = t >> 5;
    const int lane = t & 31;
    const int g  = lane >> 2;   // 0..7
    const int tg = lane & 3;    // 0..3
    const int qrow0 = blockIdx.x * 64 + warp * 16;
    const size_t bh = (size_t)(b * HH + h) * SS;

    __shared__ unsigned Ks[2][64][68];   // tf32 K bits (4g+tg conflict-free)
    __shared__ unsigned Vs[2][64][72];   // tf32 V bits (8tg+g conflict-free)
    __shared__ unsigned Ps[64][68];      // tf32 P (per-warp 16-row slabs)

    auto load_kv = [&](int kt, int bufi) {
#pragma unroll
        for (int i = 0; i < 8; i++) {
            int idx = t + i * 128;
            int r = idx >> 4;
            int c = (idx & 15) * 4;
            cp16(smem_u32(&Ks[bufi][r][c]), g_k + (bh + kt + r) * DH + c);
            cp16(smem_u32(&Vs[bufi][r][c]), g_v + (bh + kt + r) * DH + c);
        }
    };

    // Q fragments: tf32 bits straight from gmem (already scaled 1/8).
    unsigned qh[8][4];
    {
        const unsigned* Q = (const unsigned*)(g_q + (bh + qrow0) * DH);
#pragma unroll
        for (int kb = 0; kb < 8; kb++) {
            qh[kb][0] = Q[g * DH + kb * 8 + tg];
            qh[kb][1] = Q[(g + 8) * DH + kb * 8 + tg];
            qh[kb][2] = Q[g * DH + kb * 8 + tg + 4];
            qh[kb][3] = Q[(g + 8) * DH + kb * 8 + tg + 4];
        }
    }

    float o[8][4];
#pragma unroll
    for (int ni = 0; ni < 8; ni++)
#pragma unroll
        for (int e = 0; e < 4; e++) o[ni][e] = 0.f;
    float mi0 = -1e30f, mi8 = -1e30f, li0 = 0.f, li8 = 0.f;

    load_kv(0, 0);  CP_COMMIT();
    load_kv(64, 1); CP_COMMIT();

    for (int it = 0; it < 32; it++) {
        CP_WAIT1();
        __syncthreads();
        const int bi = it & 1;

        // S = Q * K^T (single tf32), warp computes 16x64 scores.
        float s[8][4];
#pragma unroll
        for (int ni = 0; ni < 8; ni++)
#pragma unroll
            for (int e = 0; e < 4; e++) s[ni][e] = 0.f;

#pragma unroll
        for (int kb = 0; kb < 8; kb++) {
#pragma unroll
            for (int ni = 0; ni < 8; ni++) {
                unsigned b0h = Ks[bi][ni * 8 + g][kb * 8 + tg];
                unsigned b1h = Ks[bi][ni * 8 + g][kb * 8 + tg + 4];
                mma_tf32(s[ni][0], s[ni][1], s[ni][2], s[ni][3],
                         qh[kb][0], qh[kb][1], qh[kb][2], qh[kb][3], b0h, b1h);
            }
        }

        // Online softmax. Rows: g (elements 0,1) and g+8 (elements 2,3).
        float t0 = mi0, t8 = mi8;
#pragma unroll
        for (int ni = 0; ni < 8; ni++) {
            t0 = fmaxf(t0, fmaxf(s[ni][0], s[ni][1]));
            t8 = fmaxf(t8, fmaxf(s[ni][2], s[ni][3]));
        }
        t0 = fmaxf(t0, __shfl_xor_sync(0xffffffffu, t0, 1));
        t0 = fmaxf(t0, __shfl_xor_sync(0xffffffffu, t0, 2));
        t8 = fmaxf(t8, __shfl_xor_sync(0xffffffffu, t8, 1));
        t8 = fmaxf(t8, __shfl_xor_sync(0xffffffffu, t8, 2));

        float c0 = __expf(mi0 - t0);
        float c8 = __expf(mi8 - t8);
        mi0 = t0; mi8 = t8;
        li0 *= c0; li8 *= c8;

        float rs0 = 0.f, rs8 = 0.f;
#pragma unroll
        for (int ni = 0; ni < 8; ni++) {
            o[ni][0] *= c0; o[ni][1] *= c0;
            o[ni][2] *= c8; o[ni][3] *= c8;
            float p0 = __expf(s[ni][0] - mi0);
            float p1 = __expf(s[ni][1] - mi0);
            float p2 = __expf(s[ni][2] - mi8);
            float p3 = __expf(s[ni][3] - mi8);
            rs0 += p0 + p1;
            rs8 += p2 + p3;
            Ps[warp * 16 + g][ni * 8 + 2 * tg]         = f2tf32(p0);
            Ps[warp * 16 + g][ni * 8 + 2 * tg + 1]     = f2tf32(p1);
            Ps[warp * 16 + 8 + g][ni * 8 + 2 * tg]     = f2tf32(p2);
            Ps[warp * 16 + 8 + g][ni * 8 + 2 * tg + 1] = f2tf32(p3);
        }
        li0 += rs0; li8 += rs8;
        __syncwarp();

        // O += P * V (tf32; P and V already tf32 bits, pure LDS + HMMA).
#pragma unroll
        for (int kb = 0; kb < 8; kb++) {
            unsigned a0 = Ps[warp * 16 + g][kb * 8 + tg];
            unsigned a1 = Ps[warp * 16 + 8 + g][kb * 8 + tg];
            unsigned a2 = Ps[warp * 16 + g][kb * 8 + tg + 4];
            unsigned a3 = Ps[warp * 16 + 8 + g][kb * 8 + tg + 4];
#pragma unroll
            for (int ni = 0; ni < 8; ni++) {
                mma_tf32(o[ni][0], o[ni][1], o[ni][2], o[ni][3],
                         a0, a1, a2, a3,
                         Vs[bi][kb * 8 + tg][ni * 8 + g],
                         Vs[bi][kb * 8 + tg + 4][ni * 8 + g]);
            }
        }

        __syncthreads();
        if (it < 30) load_kv((it + 2) * 64, bi);
        CP_COMMIT();
    }

    li0 += __shfl_xor_sync(0xffffffffu, li0, 1);
    li0 += __shfl_xor_sync(0xffffffffu, li0, 2);
    li8 += __shfl_xor_sync(0xffffffffu, li8, 1);
    li8 += __shfl_xor_sync(0xffffffffu, li8, 2);
    float inv0 = 1.f / li0;
    float inv8 = 1.f / li8;

    float* O0 = g_att + ((size_t)b * SS + qrow0 + g) * DD + h * DH;
    float* O8 = g_att + ((size_t)b * SS + qrow0 + 8 + g) * DD + h * DH;
#pragma unroll
    for (int ni = 0; ni < 8; ni++) {
        *(float2*)(O0 + ni * 8 + 2 * tg) = make_float2(o[ni][0] * inv0, o[ni][1] * inv0);
        *(float2*)(O8 + ni * 8 + 2 * tg) = make_float2(o[ni][2] * inv8, o[ni][3] * inv8);
    }
}

extern "C" void kernel_launch(void* const* d_in, const int* in_sizes, int n_in,
                              void* d_out, int out_size) {
    const float* x  = (const float*)d_in[0];
    const float* wq = (const float*)d_in[1];
    const float* wk = (const float*)d_in[2];
    const float* wv = (const float*)d_in[3];
    const float* wo = (const float*)d_in[4];
    const float* bo = (const float*)d_in[5];
    float* out = (float*)d_out;

    dim3 gqkv(DD / 128, MM / 128, 3);   // (8, 32, 3) fused Q/K/V projections
    gemm_tf32<<<gqkv, 256>>>(x, wq, wk, wv, nullptr, nullptr, 0);

    dim3 ga(SS / 64, HH, BB);           // (32, 16, 2)
    attn_mma<<<ga, 128>>>();

    dim3 go(DD / 128, MM / 128, 1);
    gemm_tf32<<<go, 256>>>(nullptr, wo, nullptr, nullptr, bo, out, 3);
}